// round 17
// baseline (speedup 1.0000x reference)
#include <cuda_runtime.h>
#include <cuda_bf16.h>
#include <stdint.h>
#include <math.h>

#define BB 16
#define TT 2048
#define DD 256

// Certification threshold. If every row/col max m has computed bf16 bound
// >= 6.5, then true m >= 6.0, so tanh(m) >= 1 - 1.2e-5; softmax over values
// within eps of 1.0 is within ~2*eps relative of uniform, so the exact mean
// matches the reference to ~2.4e-5 relative (threshold includes >=0.5 margin
// for bf16-GEMM bound error). 128 samples/max at this threshold: P(miss) ~ 1e-7.
#define CERT_THRESH 6.5f

// ---------------- scratch (static __device__ arrays; no runtime allocation) ----
__device__ __nv_bfloat16 g_qb[BB*TT*DD];    // q in bf16
__device__ __nv_bfloat16 g_ab[BB*TT*DD];    // a in bf16
__device__ __nv_bfloat16 g_Ut[DD*DD];       // U^T in bf16 (Ut[e][d] = U[d][e])
__device__ __nv_bfloat16 g_Ub[DD*DD];       // U in bf16 (row-major)
__device__ __nv_bfloat16 g_qU[BB*TT*DD];    // qU in bf16 (rows mi=0/batch + gated rest)
__device__ __nv_bfloat16 g_Wt[BB*128*DD];   // Wt[b][j][d], j = a-rows 0..127
__device__ unsigned      g_rmax[BB*TT];     // encoded float max per q-row
__device__ unsigned      g_cmax[BB*TT];     // encoded float max per a-col
__device__ float         g_meanpart[1024*4*DD]; // per-(chunk,rowgroup) mean partials
__device__ float         g_mean2[256*DD];   // stage-1 reduced mean partials

// ---------------- helpers ----------------
__device__ __forceinline__ uint32_t smem_u32(const void* p) {
    uint32_t r;
    asm("{ .reg .u64 t; cvta.to.shared.u64 t, %1; cvt.u32.u64 %0, t; }"
        : "=r"(r) : "l"(p));
    return r;
}

__device__ __forceinline__ void cpasync16(uint32_t s, const void* g) {
    asm volatile("cp.async.cg.shared.global [%0], [%1], 16;" :: "r"(s), "l"(g) : "memory");
}
#define CP_COMMIT() asm volatile("cp.async.commit_group;" ::: "memory")
#define CP_WAIT0()  asm volatile("cp.async.wait_group 0;" ::: "memory")

__device__ __forceinline__ void ldmx4(uint32_t addr, uint32_t& r0, uint32_t& r1,
                                      uint32_t& r2, uint32_t& r3) {
    asm volatile("ldmatrix.sync.aligned.m8n8.x4.shared.b16 {%0,%1,%2,%3}, [%4];"
                 : "=r"(r0), "=r"(r1), "=r"(r2), "=r"(r3) : "r"(addr));
}

__device__ __forceinline__ void mma16816(float* c, uint32_t a0, uint32_t a1,
                                         uint32_t a2, uint32_t a3,
                                         uint32_t b0, uint32_t b1) {
    asm volatile(
        "mma.sync.aligned.m16n8k16.row.col.f32.bf16.bf16.f32 "
        "{%0,%1,%2,%3}, {%4,%5,%6,%7}, {%8,%9}, {%0,%1,%2,%3};"
        : "+f"(c[0]), "+f"(c[1]), "+f"(c[2]), "+f"(c[3])
        : "r"(a0), "r"(a1), "r"(a2), "r"(a3), "r"(b0), "r"(b1));
}

__device__ __forceinline__ unsigned encf(float f) {
    unsigned u = __float_as_uint(f);
    return (u & 0x80000000u) ? ~u : (u | 0x80000000u);
}
__device__ __forceinline__ float decf(unsigned e) {
    unsigned u = (e & 0x80000000u) ? (e & 0x7FFFFFFFu) : ~e;
    return __uint_as_float(u);
}

// Inline certification verdict (CTA-collective). Callers run strictly after
// kCert in stream order, so g_rmax/g_cmax are final; every CTA computes the
// SAME deterministic verdict -> no global flag, no cross-kernel ordering.
// Returns nonzero if fallback is needed.
__device__ __forceinline__ int cert_fail() {
    __shared__ unsigned credu[256];
    int tid = threadIdx.x;
    unsigned m = 0xFFFFFFFFu;
    const uint4* r4 = (const uint4*)g_rmax;
    const uint4* c4 = (const uint4*)g_cmax;
    #pragma unroll 4
    for (int i = tid; i < 8192; i += 256) {
        uint4 v = r4[i];
        m = min(m, min(min(v.x, v.y), min(v.z, v.w)));
        uint4 w = c4[i];
        m = min(m, min(min(w.x, w.y), min(w.z, w.w)));
    }
    credu[tid] = m;
    __syncthreads();
    for (int s = 128; s > 0; s >>= 1) {
        if (tid < s) credu[tid] = min(credu[tid], credu[tid + s]);
        __syncthreads();
    }
    unsigned gm = credu[0];
    __syncthreads();
    return decf(gm) < CERT_THRESH;
}

// ---------------- GEMM core: C[128x128] = A[128x256] * B[128x256]^T -----------
#define GEMM_SMEM 65536

__device__ __forceinline__ void load_chunk(uint32_t smb, int buf,
                                           const __nv_bfloat16* __restrict__ A,
                                           const __nv_bfloat16* __restrict__ Bm,
                                           int ck, int tid) {
    const __nv_bfloat16* Ac = A + ck * 64;
    const __nv_bfloat16* Bc = Bm + ck * 64;
    #pragma unroll
    for (int i = 0; i < 4; i++) {
        int v = tid + i * 256;
        int row = v >> 3, kv = v & 7;
        uint32_t o = (uint32_t)row * 128u + (uint32_t)((kv ^ (row & 7)) * 16);
        const size_t goff = (size_t)row * DD + (size_t)kv * 8;
        cpasync16(smb + buf * 16384 + o, Ac + goff);
        cpasync16(smb + 32768 + buf * 16384 + o, Bc + goff);
    }
}

// Single-sync double-buffered pipeline (proven config).
__device__ __forceinline__ void gemm_mainloop(uint32_t smb, const __nv_bfloat16* A,
                                              const __nv_bfloat16* Bm, int tid,
                                              float acc[4][4][4]) {
    const int lid = tid & 31, w = tid >> 5;
    const int wm = (w >> 2) * 64, wn = (w & 3) * 32;
    const int lrow = lid & 15;
    const uint32_t khalf = (uint32_t)(lid >> 4) * 16u;
    const uint32_t rxor = (uint32_t)(lrow & 7) * 16u;

    uint32_t arow[4], brow[2];
    #pragma unroll
    for (int mt = 0; mt < 4; mt++) arow[mt] = (uint32_t)(wm + mt * 16 + lrow) * 128u;
    #pragma unroll
    for (int np = 0; np < 2; np++) brow[np] = (uint32_t)(wn + np * 16 + lrow) * 128u;

    load_chunk(smb, 0, A, Bm, 0, tid);
    CP_COMMIT();

    #pragma unroll
    for (int ck = 0; ck < 4; ck++) {
        CP_WAIT0();
        __syncthreads();
        if (ck + 1 < 4) {
            load_chunk(smb, (ck + 1) & 1, A, Bm, ck + 1, tid);
            CP_COMMIT();
        }

        const uint32_t abase = smb + (ck & 1) * 16384;
        const uint32_t bbase = smb + 32768 + (ck & 1) * 16384;

        #pragma unroll
        for (int kk = 0; kk < 4; kk++) {
            const uint32_t kswz = ((uint32_t)kk * 32u + khalf) ^ rxor;
            uint32_t a[4][4];
            #pragma unroll
            for (int mt = 0; mt < 4; mt++)
                ldmx4(abase + arow[mt] + kswz, a[mt][0], a[mt][1], a[mt][2], a[mt][3]);
            uint32_t b[4][2];
            #pragma unroll
            for (int np = 0; np < 2; np++) {
                uint32_t r0, r1, r2, r3;
                ldmx4(bbase + brow[np] + kswz, r0, r1, r2, r3);
                b[np * 2 + 0][0] = r0; b[np * 2 + 0][1] = r2;
                b[np * 2 + 1][0] = r1; b[np * 2 + 1][1] = r3;
            }
            #pragma unroll
            for (int mt = 0; mt < 4; mt++)
                #pragma unroll
                for (int nt = 0; nt < 4; nt++)
                    mma16816(acc[mt][nt], a[mt][0], a[mt][1], a[mt][2], a[mt][3],
                             b[nt][0], b[nt][1]);
        }
    }
}

// shared epilogues ------------------------------------------------------------
__device__ __forceinline__ void epi_store_bf16(const float acc[4][4][4], int tid,
                                               __nv_bfloat16* dstbase, int rowOff,
                                               int colOff, int rowStride) {
    const int lid = tid & 31, w = tid >> 5;
    const int wm = (w >> 2) * 64, wn = (w & 3) * 32;
    const int g = lid >> 2, tg = lid & 3;
    #pragma unroll
    for (int mt = 0; mt < 4; mt++) {
        int row0 = rowOff + wm + mt * 16 + g;
        #pragma unroll
        for (int nt = 0; nt < 4; nt++) {
            int col = colOff + wn + nt * 8 + 2 * tg;
            __nv_bfloat162 p0 = __floats2bfloat162_rn(acc[mt][nt][0], acc[mt][nt][1]);
            __nv_bfloat162 p1 = __floats2bfloat162_rn(acc[mt][nt][2], acc[mt][nt][3]);
            *reinterpret_cast<unsigned*>(dstbase + (size_t)row0 * rowStride + col) =
                *reinterpret_cast<unsigned*>(&p0);
            *reinterpret_cast<unsigned*>(dstbase + (size_t)(row0 + 8) * rowStride + col) =
                *reinterpret_cast<unsigned*>(&p1);
        }
    }
}

__device__ __forceinline__ void epi_max(const float acc[4][4][4], int tid,
                                        int rowBase, int colBase) {
    const int lid = tid & 31, w = tid >> 5;
    const int wm = (w >> 2) * 64, wn = (w & 3) * 32;
    const int g = lid >> 2, tg = lid & 3;
    const int rb = rowBase + wm;
    const int cb = colBase + wn;

    #pragma unroll
    for (int mt = 0; mt < 4; mt++) {
        float r0 = -3.0e38f, r1 = -3.0e38f;
        #pragma unroll
        for (int nt = 0; nt < 4; nt++) {
            r0 = fmaxf(r0, fmaxf(acc[mt][nt][0], acc[mt][nt][1]));
            r1 = fmaxf(r1, fmaxf(acc[mt][nt][2], acc[mt][nt][3]));
        }
        r0 = fmaxf(r0, __shfl_xor_sync(0xffffffffu, r0, 1));
        r0 = fmaxf(r0, __shfl_xor_sync(0xffffffffu, r0, 2));
        r1 = fmaxf(r1, __shfl_xor_sync(0xffffffffu, r1, 1));
        r1 = fmaxf(r1, __shfl_xor_sync(0xffffffffu, r1, 2));
        if (tg == 0) {
            atomicMax(&g_rmax[rb + mt * 16 + g], encf(r0));
            atomicMax(&g_rmax[rb + mt * 16 + g + 8], encf(r1));
        }
    }
    #pragma unroll
    for (int nt = 0; nt < 4; nt++) {
        float c0 = -3.0e38f, c1 = -3.0e38f;
        #pragma unroll
        for (int mt = 0; mt < 4; mt++) {
            c0 = fmaxf(c0, fmaxf(acc[mt][nt][0], acc[mt][nt][2]));
            c1 = fmaxf(c1, fmaxf(acc[mt][nt][1], acc[mt][nt][3]));
        }
        #pragma unroll
        for (int s = 4; s < 32; s <<= 1) {
            c0 = fmaxf(c0, __shfl_xor_sync(0xffffffffu, c0, s));
            c1 = fmaxf(c1, __shfl_xor_sync(0xffffffffu, c1, s));
        }
        if (g == 0) {
            atomicMax(&g_cmax[cb + nt * 8 + 2 * tg], encf(c0));
            atomicMax(&g_cmax[cb + nt * 8 + 2 * tg + 1], encf(c1));
        }
    }
}

#define ACC_DECL_ZERO(acc) \
    float acc[4][4][4]; \
    _Pragma("unroll") for (int _i = 0; _i < 4; _i++) \
    _Pragma("unroll") for (int _j = 0; _j < 4; _j++) \
    _Pragma("unroll") for (int _r = 0; _r < 4; _r++) acc[_i][_j][_r] = 0.0f;

// ---------------- k0: convert fp32->bf16 + mean partials + aux ---------------
__global__ void __launch_bounds__(256) k0_convert(const float* __restrict__ q,
                                                  const float* __restrict__ a,
                                                  const float* __restrict__ U) {
    int bx = blockIdx.x;
    int tid = threadIdx.x;

    if (bx >= 1024) {
        int bz = bx - 1024;
        if (bz < 64) {
            int i0 = (bz * 256 + tid) * 2;
            g_rmax[i0] = 0u; g_rmax[i0 + 1] = 0u;
            g_cmax[i0] = 0u; g_cmax[i0 + 1] = 0u;
        } else if (bz < 68) {
            int blk = bz - 64;   // Ut
            #pragma unroll 4
            for (int it = 0; it < 64; it++) {
                int i = blk * 16384 + it * 256 + tid;
                int d = i >> 8, e = i & 255;
                g_Ut[e * DD + d] = __float2bfloat16(U[i]);
            }
        } else {
            int blk = bz - 68;   // Ub (straight)
            #pragma unroll 4
            for (int it = 0; it < 64; it++) {
                int i = blk * 16384 + it * 256 + tid;
                g_Ub[i] = __float2bfloat16(U[i]);
            }
        }
        return;
    }

    int tensor = bx >> 9;
    int local = bx & 511;
    int b = local >> 5;
    int chunk = local & 31;   // 64-row chunk
    const float4* src = (const float4*)((tensor ? a : q) +
                        ((size_t)b * TT + (size_t)chunk * 64) * DD);
    uint2* dst = (uint2*)((tensor ? g_ab : g_qb) +
                 ((size_t)b * TT + (size_t)chunk * 64) * DD);

    const int dvec = tid & 63;          // float4 index within row
    const int rg = tid >> 6;            // row group 0..3
    float4 s = make_float4(0.f, 0.f, 0.f, 0.f);
    #pragma unroll 4
    for (int it = 0; it < 16; it++) {
        int row = it * 4 + rg;
        float4 v = src[(size_t)row * 64 + dvec];
        s.x += v.x; s.y += v.y; s.z += v.z; s.w += v.w;
        __nv_bfloat162 lo = __floats2bfloat162_rn(v.x, v.y);
        __nv_bfloat162 hi = __floats2bfloat162_rn(v.z, v.w);
        uint2 o;
        o.x = *reinterpret_cast<unsigned*>(&lo);
        o.y = *reinterpret_cast<unsigned*>(&hi);
        dst[(size_t)row * 64 + dvec] = o;
    }
    float4* mp = (float4*)&g_meanpart[((size_t)bx * 4 + rg) * DD];
    mp[dvec] = s;
}

// ---------------- kWqa: kW(tileM=0) + k1a(mi=0) tiles + mean stage-1 ----------
__global__ void __launch_bounds__(256, 2) kWqa() {
    extern __shared__ char sm[];
    int tid = threadIdx.x;
    int bid = blockIdx.x;

    if (bid >= 64) {
        int v = bid - 64;   // 0..255
        float s = 0.0f;
        #pragma unroll
        for (int j = 0; j < 16; j++)
            s += g_meanpart[(size_t)(v * 16 + j) * DD + tid];
        g_mean2[(size_t)v * DD + tid] = s;
        return;
    }

    uint32_t smb = smem_u32(sm);
    int b = bid >> 2;
    int s = bid & 3;

    ACC_DECL_ZERO(acc);
    if (s < 2) {
        int tileN = s;   // Wt[b] for a-rows 0..127, d block tileN
        gemm_mainloop(smb, g_ab + (size_t)b * TT * DD,
                      g_Ub + (size_t)tileN * 128 * DD, tid, acc);
        epi_store_bf16(acc, tid, g_Wt + (size_t)b * 128 * DD,
                       0, tileN * 128, DD);
    } else {
        int tileN = s - 2;   // qU rows b*16 (mi=0)
        gemm_mainloop(smb, g_qb + (size_t)(b * 16) * 128 * DD,
                      g_Ut + (size_t)tileN * 128 * DD, tid, acc);
        epi_store_bf16(acc, tid, g_qU, (b * 16) * 128, tileN * 128, DD);
    }
}

// ---------------- kCert: kG (128-col row samples, exact cols 0..127) +
//                   col-cert (cols 128..2047 sampled on q-rows 0..127) --------
__global__ void __launch_bounds__(256, 2) kCert() {
    extern __shared__ char sm[];
    uint32_t smb = smem_u32(sm);
    int tid = threadIdx.x;
    int b = blockIdx.x / 31;
    int s = blockIdx.x % 31;

    ACC_DECL_ZERO(acc);
    if (s < 16) {
        int j = s;
        gemm_mainloop(smb, g_qb + (size_t)(b * 16 + j) * 128 * DD,
                      g_Wt + (size_t)b * 128 * DD, tid, acc);
        epi_max(acc, tid, (b * 16 + j) * 128, b * TT);
    } else {
        int nb = 1 + (s - 16);   // 1..15
        gemm_mainloop(smb, g_qU + (size_t)(b * 16) * 128 * DD,
                      g_ab + ((size_t)b * TT + (size_t)nb * 128) * DD, tid, acc);
        epi_max(acc, tid, b * TT, b * TT + nb * 128);
    }
}

// ---------------- gated fallback: complete qU mi=1..15 (15 tiles per CTA) -----
// 32 CTAs: tileN = bid&1, b = bid>>1. Verdict recomputed inline (no flag).
__global__ void __launch_bounds__(256, 2) k1_qU_gated() {
    if (!cert_fail()) return;
    extern __shared__ char sm[];
    uint32_t smb = smem_u32(sm);
    int tid = threadIdx.x;
    int tileN = blockIdx.x & 1;
    int b = blockIdx.x >> 1;       // 0..15
    for (int i = 0; i < 15; i++) {
        int tileM = b * 16 + 1 + i;
        ACC_DECL_ZERO(acc);
        gemm_mainloop(smb, g_qb + (size_t)tileM * 128 * DD,
                      g_Ut + (size_t)tileN * 128 * DD, tid, acc);
        epi_store_bf16(acc, tid, g_qU, tileM * 128, tileN * 128, DD);
        __syncthreads();
    }
}

// ---------------- gated fallback: tiles (mi 1..15, nb 1..15), 225 per CTA -----
// 16 CTAs (b = bid). Fallback-only; dispatch cost is what matters.
__global__ void __launch_bounds__(256, 2) k2_gated() {
    if (!cert_fail()) return;
    extern __shared__ char sm[];
    uint32_t smb = smem_u32(sm);
    int tid = threadIdx.x;
    int b = blockIdx.x;
    for (int nb = 1; nb < 16; nb++) {
        for (int mi = 1; mi < 16; mi++) {
            ACC_DECL_ZERO(acc);
            gemm_mainloop(smb, g_qU + ((size_t)b * TT + (size_t)mi * 128) * DD,
                          g_ab + ((size_t)b * TT + (size_t)nb * 128) * DD, tid, acc);
            epi_max(acc, tid, b * TT + mi * 128, b * TT + nb * 128);
            __syncthreads();
        }
    }
}

// ---------------- kOutFinal: certified means OR fallback softmax+pool ---------
__global__ void kOutFinal(const float* __restrict__ q, const float* __restrict__ a,
                          float* __restrict__ out) {
    __shared__ float ws[TT];
    __shared__ float red[256];
    int tid = threadIdx.x;
    int which = blockIdx.x >> 4;
    int b = blockIdx.x & 15;

    int need_full = cert_fail();

    if (!need_full) {
        int base = which * 128 + b * 8;
        float s = 0.0f;
        #pragma unroll
        for (int j = 0; j < 8; j++) s += g_mean2[(size_t)(base + j) * DD + tid];
        out[which * BB * DD + b * DD + tid] = s * (1.0f / (float)TT);
        return;
    }

    const unsigned* src = (which ? g_cmax : g_rmax) + b * TT;
    float tv[8];
    #pragma unroll
    for (int i = 0; i < 8; i++) tv[i] = tanhf(decf(src[i * 256 + tid]));

    float lm = tv[0];
    #pragma unroll
    for (int i = 1; i < 8; i++) lm = fmaxf(lm, tv[i]);
    red[tid] = lm;
    __syncthreads();
    for (int s = 128; s > 0; s >>= 1) {
        if (tid < s) red[tid] = fmaxf(red[tid], red[tid + s]);
        __syncthreads();
    }
    float mx = red[0];
    __syncthreads();

    float ls = 0.0f;
    #pragma unroll
    for (int i = 0; i < 8; i++) ls += expf(tv[i] - mx);
    red[tid] = ls;
    __syncthreads();
    for (int s = 128; s > 0; s >>= 1) {
        if (tid < s) red[tid] += red[tid + s];
        __syncthreads();
    }
    float inv = 1.0f / red[0];
    __syncthreads();

    #pragma unroll
    for (int i = 0; i < 8; i++) ws[i * 256 + tid] = expf(tv[i] - mx) * inv;
    __syncthreads();

    const float* basep = (which ? a : q) + (size_t)b * TT * DD + tid;
    float acc = 0.0f;
    for (int t = 0; t < TT; t++) acc += ws[t] * basep[(size_t)t * DD];
    out[which * BB * DD + b * DD + tid] = acc;
}

// ---------------- launch ------------------------------------------------------
extern "C" void kernel_launch(void* const* d_in, const int* in_sizes, int n_in,
                              void* d_out, int out_size) {
    int ui = 2;
    for (int i = 0; i < n_in; i++)
        if (in_sizes[i] == DD * DD) ui = i;
    const float* ptrs[3];
    int k = 0;
    for (int i = 0; i < n_in && k < 3; i++)
        if (i != ui) ptrs[k++] = (const float*)d_in[i];
    const float* q = ptrs[0];
    const float* a = ptrs[1];
    const float* U = (const float*)d_in[ui];
    float* out = (float*)d_out;

    static int init_done = 0;
    if (!init_done) {
        cudaFuncSetAttribute(kWqa,        cudaFuncAttributeMaxDynamicSharedMemorySize, GEMM_SMEM);
        cudaFuncSetAttribute(kCert,       cudaFuncAttributeMaxDynamicSharedMemorySize, GEMM_SMEM);
        cudaFuncSetAttribute(k1_qU_gated, cudaFuncAttributeMaxDynamicSharedMemorySize, GEMM_SMEM);
        cudaFuncSetAttribute(k2_gated,    cudaFuncAttributeMaxDynamicSharedMemorySize, GEMM_SMEM);
        init_done = 1;
    }

    // converts + mean partials + U^T/U + zero maxes (no-smem, high occupancy)
    k0_convert<<<1096, 256>>>(q, a, U);
    // Wt (a-rows 0..127) + qU (mi=0) + mean stage-1 filling idle SMs
    kWqa<<<320, 256, GEMM_SMEM>>>();
    // kG (row samples on 128 cols; exact col maxes 0..127) + col-cert (496 CTAs)
    kCert<<<496, 256, GEMM_SMEM>>>();
    // fallback GEMMs (verdict recomputed inline; self-disabled when certified)
    k1_qU_gated<<<32, 256, GEMM_SMEM>>>();
    k2_gated<<<16, 256, GEMM_SMEM>>>();
    // final output: certified means OR fallback softmax+pool (inline verdict)
    kOutFinal<<<32, 256>>>(q, a, out);
    (void)out_size;
}